// round 5
// baseline (speedup 1.0000x reference)
#include <cuda_runtime.h>
#include <math.h>

#define NBS 64
#define NT  2048
#define NJ  24
#define ROW 99        // NJ*4 + 3
#define TPB 128

__device__ double g_acc;

__global__ void init_k() { g_acc = 0.0; }

__device__ __forceinline__ void quat2mat(float w, float x, float y, float z, float R[9]) {
    float s = 2.0f / (w*w + x*x + y*y + z*z);
    float xx = x*x, yy = y*y, zz = z*z;
    float xy = x*y, xz = x*z, yz = y*z;
    float wx = w*x, wy = w*y, wz = w*z;
    R[0] = 1.0f - s*(yy + zz); R[1] = s*(xy - wz);        R[2] = s*(xz + wy);
    R[3] = s*(xy + wz);        R[4] = 1.0f - s*(xx + zz); R[5] = s*(yz - wx);
    R[6] = s*(xz - wy);        R[7] = s*(yz + wx);        R[8] = 1.0f - s*(xx + yy);
}

__global__ __launch_bounds__(TPB)
void motion_loss_k(const float* __restrict__ Ym, const float* __restrict__ Xm,
                   const float* __restrict__ Yt, const float* __restrict__ Xt)
{
    extern __shared__ float smem[];
    float* sX = smem;              // TPB*ROW
    float* sY = smem + TPB*ROW;    // TPB*ROW
    __shared__ float sXt[NJ*3], sYt[NJ*3];
    __shared__ float sRed[TPB/32];

    const int b   = blockIdx.y;
    const int t0  = blockIdx.x * TPB;
    const int tid = threadIdx.x;

    if (tid < NJ*3) {
        sXt[tid] = Xt[b*NJ*3 + tid];
        sYt[tid] = Yt[b*NJ*3 + tid];
    }

    const size_t base = ((size_t)b*NT + t0) * ROW;
    #pragma unroll 4
    for (int i = tid; i < TPB*ROW; i += TPB) {
        sX[i] = Xm[base + i];
        sY[i] = Ym[base + i];
    }
    __syncthreads();

    const float* x = sX + tid*ROW;
    const float* y = sY + tid*ROW;

    float s_rot = 0.f, s_gtr = 0.f, s_pos = 0.f;
    {
        float d0 = y[96]-x[96], d1 = y[97]-x[97], d2 = y[98]-x[98];
        s_pos = d0*d0 + d1*d1 + d2*d2;
    }

    // Register-resident FK state (SROA after full unroll; only live joints kept)
    float gRx[NJ][9], gRy[NJ][9];
    float gTx[NJ][3], gTy[NJ][3];

    constexpr int  TOPO[NJ]    = {-1,0,0,0,1,2,3,4,5,6,7,8,9,9,9,12,13,14,16,17,18,19,20,21};
    constexpr bool NONLEAF[NJ] = {true,true,true,true,true,true,true,true,true,true,
                                  false,false,true,true,true,false,
                                  true,true,true,true,true,true,false,false};

    #pragma unroll
    for (int i = 0; i < NJ; i++) {
        float xw = x[4*i+0], xa = x[4*i+1], xb = x[4*i+2], xc = x[4*i+3];
        float yw = y[4*i+0], ya = y[4*i+1], yb = y[4*i+2], yc = y[4*i+3];

        // rotation (normalized-quaternion) MSE contribution
        float dx  = xw*xw + xa*xa + xb*xb + xc*xc;
        float dy  = yw*yw + ya*ya + yb*yb + yc*yc;
        float ivx = 1.0f / fmaxf(sqrtf(dx), 1e-12f);
        float ivy = 1.0f / fmaxf(sqrtf(dy), 1e-12f);
        float e;
        e = yw*ivy - xw*ivx; s_rot += e*e;
        e = ya*ivy - xa*ivx; s_rot += e*e;
        e = yb*ivy - xb*ivx; s_rot += e*e;
        e = yc*ivy - xc*ivx; s_rot += e*e;

        if (i == 0) {
            quat2mat(xw, xa, xb, xc, gRx[0]);
            quat2mat(yw, ya, yb, yc, gRy[0]);
            gTx[0][0] = x[96]; gTx[0][1] = x[97]; gTx[0][2] = x[98];
            gTy[0][0] = y[96]; gTy[0][1] = y[97]; gTy[0][2] = y[98];
        } else {
            const int p = TOPO[i];
            if (NONLEAF[i]) {
                float Rl[9];
                quat2mat(xw, xa, xb, xc, Rl);
                #pragma unroll
                for (int r = 0; r < 3; r++)
                    #pragma unroll
                    for (int c = 0; c < 3; c++)
                        gRx[i][r*3+c] = gRx[p][r*3+0]*Rl[0*3+c]
                                      + gRx[p][r*3+1]*Rl[1*3+c]
                                      + gRx[p][r*3+2]*Rl[2*3+c];
                quat2mat(yw, ya, yb, yc, Rl);
                #pragma unroll
                for (int r = 0; r < 3; r++)
                    #pragma unroll
                    for (int c = 0; c < 3; c++)
                        gRy[i][r*3+c] = gRy[p][r*3+0]*Rl[0*3+c]
                                      + gRy[p][r*3+1]*Rl[1*3+c]
                                      + gRy[p][r*3+2]*Rl[2*3+c];
            }
            float vx0 = sXt[3*i+0], vx1 = sXt[3*i+1], vx2 = sXt[3*i+2];
            float vy0 = sYt[3*i+0], vy1 = sYt[3*i+1], vy2 = sYt[3*i+2];
            #pragma unroll
            for (int r = 0; r < 3; r++) {
                gTx[i][r] = gRx[p][r*3+0]*vx0 + gRx[p][r*3+1]*vx1 + gRx[p][r*3+2]*vx2 + gTx[p][r];
                gTy[i][r] = gRy[p][r*3+0]*vy0 + gRy[p][r*3+1]*vy1 + gRy[p][r*3+2]*vy2 + gTy[p][r];
            }
        }
        #pragma unroll
        for (int r = 0; r < 3; r++) {
            float d = gTy[i][r] - gTx[i][r];
            s_gtr += d*d;
        }
    }

    const float INV_ROT = 1.0f / (float)((size_t)NBS*NT*NJ*4);
    const float F_GTR   = 2.5f / (float)((size_t)NBS*NT*NJ*3);
    const float INV_POS = 1.0f / (float)((size_t)NBS*NT*3);
    float partial = s_rot*INV_ROT + s_gtr*F_GTR + s_pos*INV_POS;

    #pragma unroll
    for (int o = 16; o > 0; o >>= 1)
        partial += __shfl_down_sync(0xffffffffu, partial, o);
    if ((tid & 31) == 0) sRed[tid >> 5] = partial;
    __syncthreads();
    if (tid == 0) {
        float bs = 0.f;
        #pragma unroll
        for (int w = 0; w < TPB/32; w++) bs += sRed[w];
        atomicAdd(&g_acc, (double)bs);
    }
}

__global__ void finish_k(float* out) { out[0] = (float)g_acc; }

extern "C" void kernel_launch(void* const* d_in, const int* in_sizes, int n_in,
                              void* d_out, int out_size)
{
    // Identify inputs by size: two big (motion, 64*2048*99) and two small (offsets, 64*24*3).
    // Pairing by order within each size class is correct for both dict-order
    // (Y_m, X_m, Y_t, X_t) and alphabetical (X_m, X_t, Y_m, Y_t) metadata — the
    // loss is invariant under a consistent Y<->X swap.
    const float* big[2]   = {nullptr, nullptr};
    const float* small[2] = {nullptr, nullptr};
    int nb = 0, ns = 0;
    for (int i = 0; i < n_in; i++) {
        if (in_sizes[i] > 100000) { if (nb < 2) big[nb++] = (const float*)d_in[i]; }
        else                      { if (ns < 2) small[ns++] = (const float*)d_in[i]; }
    }
    const float* Ym = big[0];
    const float* Xm = big[1];
    const float* Yt = small[0];
    const float* Xt = small[1];

    const int smem_bytes = 2 * TPB * ROW * (int)sizeof(float);
    cudaFuncSetAttribute(motion_loss_k, cudaFuncAttributeMaxDynamicSharedMemorySize, smem_bytes);

    init_k<<<1, 1>>>();
    dim3 grid(NT / TPB, NBS);
    motion_loss_k<<<grid, TPB, smem_bytes>>>(Ym, Xm, Yt, Xt);
    finish_k<<<1, 1>>>((float*)d_out);
}

// round 9
// speedup vs baseline: 1.2776x; 1.2776x over previous
#include <cuda_runtime.h>
#include <math.h>

#define NBS 64
#define NT  2048
#define NJ  24
#define ROW 99        // NJ*4 + 3
#define PAD 100       // padded smem row: 400 B -> 16B-aligned float4 quat loads
#define TPB 128
#define NBLK ((NBS * NT) / TPB)   // 1024

__device__ float        g_part[NBLK];
__device__ unsigned int g_cnt = 0;

__device__ __forceinline__ void q2m(float w, float xq, float yq, float zq, float s, float R[9]) {
    R[0] = 1.0f - s*(yq*yq + zq*zq); R[1] = s*(xq*yq - zq*w);        R[2] = s*(xq*zq + yq*w);
    R[3] = s*(xq*yq + zq*w);         R[4] = 1.0f - s*(xq*xq + zq*zq); R[5] = s*(yq*zq - xq*w);
    R[6] = s*(xq*zq - yq*w);         R[7] = s*(yq*zq + xq*w);         R[8] = 1.0f - s*(xq*xq + yq*yq);
}

__global__ __launch_bounds__(TPB)
void motion_loss_k(const float* __restrict__ Ym, const float* __restrict__ Xm,
                   const float* __restrict__ Yt, const float* __restrict__ Xt,
                   float* __restrict__ out)
{
    extern __shared__ float smem[];
    float* sX = smem;               // TPB*PAD
    float* sY = smem + TPB*PAD;     // TPB*PAD
    __shared__ float  sXt[NJ*3], sYt[NJ*3];
    __shared__ float  sRed[TPB/32];
    __shared__ double sRedD[TPB/32];
    __shared__ int    sLast;

    const int blk  = blockIdx.x;
    const int b    = blk >> 4;            // NT/TPB = 16 blocks per batch row
    const int t0   = (blk & 15) * TPB;
    const int tid  = threadIdx.x;
    const int wid  = tid >> 5;
    const int lane = tid & 31;

    if (tid < NJ*3) {
        sXt[tid] = Xt[b*NJ*3 + tid];
        sYt[tid] = Yt[b*NJ*3 + tid];
    }

    // Coalesced staging into padded smem rows (stride PAD=100 floats).
    const size_t base = ((size_t)b*NT + t0) * ROW;
    #pragma unroll 2
    for (int r = wid; r < TPB; r += TPB/32) {
        const float* gx = Xm + base + (size_t)r*ROW;
        const float* gy = Ym + base + (size_t)r*ROW;
        float* dx = sX + r*PAD;
        float* dy = sY + r*PAD;
        dx[lane]      = gx[lane];
        dx[lane + 32] = gx[lane + 32];
        dx[lane + 64] = gx[lane + 64];
        dy[lane]      = gy[lane];
        dy[lane + 32] = gy[lane + 32];
        dy[lane + 64] = gy[lane + 64];
        if (lane < 3) { dx[lane + 96] = gx[lane + 96]; dy[lane + 96] = gy[lane + 96]; }
    }
    __syncthreads();

    const float* x = sX + tid*PAD;
    const float* y = sY + tid*PAD;

    float s_rot = 0.f, s_gtr = 0.f, s_pos = 0.f;
    const float px0 = x[96], px1 = x[97], px2 = x[98];
    const float py0 = y[96], py1 = y[97], py2 = y[98];
    {
        float d0 = py0-px0, d1 = py1-px1, d2 = py2-px2;
        s_pos = d0*d0 + d1*d1 + d2*d2;
    }

    // Hand-allocated FK register file: interval-colored to 3 slots.
    float Rx[3][9], Ry[3][9];
    float Tx[3][3], Ty[3][3];

    constexpr int  TOPO[NJ] = {-1,0,0,0,1,2,3,4,5,6,7,8,9,9,9,12,13,14,16,17,18,19,20,21};
    constexpr int  SLOT[NJ] = { 0,1,2,0,1,2,0,1,2,0,0,0,1,2,0, 0, 2, 0, 2, 0, 2, 0, 0, 0};
    constexpr bool NL[NJ]   = { true,true,true,true,true,true,true,true,true,true,
                                false,false,true,true,true,false,
                                true,true,true,true,true,true,false,false };

    #pragma unroll
    for (int i = 0; i < NJ; i++) {
        const float4 qx = *reinterpret_cast<const float4*>(x + 4*i);
        const float4 qy = *reinterpret_cast<const float4*>(y + 4*i);

        const float dxn = qx.x*qx.x + qx.y*qx.y + qx.z*qx.z + qx.w*qx.w;
        const float dyn = qy.x*qy.x + qy.y*qy.y + qy.z*qy.z + qy.w*qy.w;
        const float ivx = rsqrtf(dxn);
        const float ivy = rsqrtf(dyn);

        // rotation (normalized-quaternion) MSE
        float e;
        e = qy.x*ivy - qx.x*ivx; s_rot += e*e;
        e = qy.y*ivy - qx.y*ivx; s_rot += e*e;
        e = qy.z*ivy - qx.z*ivx; s_rot += e*e;
        e = qy.w*ivy - qx.w*ivx; s_rot += e*e;

        const float sx = 2.0f*ivx*ivx;   // == 2/|q|^2 (reuse rsqrt, no extra MUFU)
        const float sy = 2.0f*ivy*ivy;

        if (i == 0) {
            q2m(qx.x, qx.y, qx.z, qx.w, sx, Rx[0]);
            q2m(qy.x, qy.y, qy.z, qy.w, sy, Ry[0]);
            Tx[0][0] = px0; Tx[0][1] = px1; Tx[0][2] = px2;
            Ty[0][0] = py0; Ty[0][1] = py1; Ty[0][2] = py2;
            s_gtr += s_pos;   // joint-0 gtr term equals root position diff
        } else {
            const int p = SLOT[TOPO[i]];

            const float vx0 = sXt[3*i+0], vx1 = sXt[3*i+1], vx2 = sXt[3*i+2];
            const float vy0 = sYt[3*i+0], vy1 = sYt[3*i+1], vy2 = sYt[3*i+2];

            const float tx0 = Rx[p][0]*vx0 + Rx[p][1]*vx1 + Rx[p][2]*vx2 + Tx[p][0];
            const float tx1 = Rx[p][3]*vx0 + Rx[p][4]*vx1 + Rx[p][5]*vx2 + Tx[p][1];
            const float tx2 = Rx[p][6]*vx0 + Rx[p][7]*vx1 + Rx[p][8]*vx2 + Tx[p][2];
            const float ty0 = Ry[p][0]*vy0 + Ry[p][1]*vy1 + Ry[p][2]*vy2 + Ty[p][0];
            const float ty1 = Ry[p][3]*vy0 + Ry[p][4]*vy1 + Ry[p][5]*vy2 + Ty[p][1];
            const float ty2 = Ry[p][6]*vy0 + Ry[p][7]*vy1 + Ry[p][8]*vy2 + Ty[p][2];

            const float d0 = ty0-tx0, d1 = ty1-tx1, d2 = ty2-tx2;
            s_gtr += d0*d0 + d1*d1 + d2*d2;

            if (NL[i]) {
                const int s = SLOT[i];
                float L[9], M[9];

                q2m(qx.x, qx.y, qx.z, qx.w, sx, L);
                #pragma unroll
                for (int r = 0; r < 3; r++)
                    #pragma unroll
                    for (int c = 0; c < 3; c++)
                        M[r*3+c] = Rx[p][r*3+0]*L[0*3+c]
                                 + Rx[p][r*3+1]*L[1*3+c]
                                 + Rx[p][r*3+2]*L[2*3+c];
                #pragma unroll
                for (int k = 0; k < 9; k++) Rx[s][k] = M[k];

                q2m(qy.x, qy.y, qy.z, qy.w, sy, L);
                #pragma unroll
                for (int r = 0; r < 3; r++)
                    #pragma unroll
                    for (int c = 0; c < 3; c++)
                        M[r*3+c] = Ry[p][r*3+0]*L[0*3+c]
                                 + Ry[p][r*3+1]*L[1*3+c]
                                 + Ry[p][r*3+2]*L[2*3+c];
                #pragma unroll
                for (int k = 0; k < 9; k++) Ry[s][k] = M[k];

                Tx[s][0] = tx0; Tx[s][1] = tx1; Tx[s][2] = tx2;
                Ty[s][0] = ty0; Ty[s][1] = ty1; Ty[s][2] = ty2;
            }
        }
    }

    const float INV_ROT = 1.0f / (float)((size_t)NBS*NT*NJ*4);
    const float F_GTR   = 2.5f / (float)((size_t)NBS*NT*NJ*3);
    const float INV_POS = 1.0f / (float)((size_t)NBS*NT*3);
    float partial = s_rot*INV_ROT + s_gtr*F_GTR + s_pos*INV_POS;

    #pragma unroll
    for (int o = 16; o > 0; o >>= 1)
        partial += __shfl_down_sync(0xffffffffu, partial, o);
    if (lane == 0) sRed[wid] = partial;
    __syncthreads();

    if (tid == 0) {
        float bs = sRed[0] + sRed[1] + sRed[2] + sRed[3];
        g_part[blk] = bs;
        __threadfence();
        unsigned v = atomicAdd(&g_cnt, 1u);
        sLast = (v == NBLK - 1) ? 1 : 0;
    }
    __syncthreads();

    if (sLast) {
        // Last-arriving block: reduce all per-block partials, write scalar, reset counter.
        double acc = 0.0;
        volatile float* vp = g_part;
        for (int j = tid; j < NBLK; j += TPB) acc += (double)vp[j];
        #pragma unroll
        for (int o = 16; o > 0; o >>= 1)
            acc += __shfl_down_sync(0xffffffffu, acc, o);
        if (lane == 0) sRedD[wid] = acc;
        __syncthreads();
        if (tid == 0) {
            double tot = sRedD[0] + sRedD[1] + sRedD[2] + sRedD[3];
            out[0] = (float)tot;
            g_cnt = 0;   // deterministic across graph replays
        }
    }
}

extern "C" void kernel_launch(void* const* d_in, const int* in_sizes, int n_in,
                              void* d_out, int out_size)
{
    // Identify inputs by size: two big (motion) vs two small (offsets); pairing
    // by order is correct for both dict and alphabetical metadata ordering
    // (loss is symmetric under consistent Y<->X swap).
    const float* big[2]   = {nullptr, nullptr};
    const float* small[2] = {nullptr, nullptr};
    int nb = 0, ns = 0;
    for (int i = 0; i < n_in; i++) {
        if (in_sizes[i] > 100000) { if (nb < 2) big[nb++] = (const float*)d_in[i]; }
        else                      { if (ns < 2) small[ns++] = (const float*)d_in[i]; }
    }
    const float* Ym = big[0];
    const float* Xm = big[1];
    const float* Yt = small[0];
    const float* Xt = small[1];

    const int smem_bytes = 2 * TPB * PAD * (int)sizeof(float);   // 102400 B
    static int attr_set = 0;
    if (!attr_set) {
        cudaFuncSetAttribute(motion_loss_k, cudaFuncAttributeMaxDynamicSharedMemorySize, smem_bytes);
        attr_set = 1;
    }

    motion_loss_k<<<NBLK, TPB, smem_bytes>>>(Ym, Xm, Yt, Xt, (float*)d_out);
}